// round 14
// baseline (speedup 1.0000x reference)
#include <cuda_runtime.h>
#include <cuda_fp16.h>
#include <cstdint>

// ============================================================================
// Causal attention B=4 H=16 S=2048 D=64 fp32.
// Round 14: R13 (LPT launch order, frozen-max softmax) + intra-iteration
// split-softmax pipelining on frozen iterations: exp(cols 0-31) -> PV h=0
// issued -> exp(cols 32-63) overlaps PV h=0 drain -> PV h=1.
// fp16 MMAs, ones-column row-sum, cp.async double-buffer.
// ============================================================================

#define S_LEN   2048
#define HEADS   16
#define BHT     64
#define D       64
#define BM      128
#define BN      64
#define NQT     (S_LEN / BM)    // 16
#define THREADS 128

#define KV_ELEMS (BHT * S_LEN * D)    // 8,388,608

__device__ __half g_KH[KV_ELEMS];
__device__ __half g_VH[KV_ELEMS];

#define SMB(b)     ((b) * 16384)
#define OFF_KH     0
#define OFF_VH     8192
#define SM_MASK    32768            // 2 x 256B int masks
#define SM_TOTAL   33280

__device__ __forceinline__ uint32_t smem_u32(const void* p) {
    uint32_t a;
    asm("{ .reg .u64 t; cvta.to.shared.u64 t, %1; cvt.u32.u64 %0, t; }" : "=r"(a) : "l"(p));
    return a;
}
__device__ __forceinline__ float ex2f(float x) {
    float y; asm("ex2.approx.f32 %0, %1;" : "=f"(y) : "f"(x)); return y;
}
__device__ __forceinline__ uint32_t pack_f16x2(float e0, float e1) {
    uint32_t r; asm("cvt.rn.f16x2.f32 %0, %1, %2;" : "=r"(r) : "f"(e1), "f"(e0)); return r;
}
__device__ __forceinline__ uint32_t ex2_f16x2(uint32_t x) {
    uint32_t r; asm("ex2.approx.f16x2 %0, %1;" : "=r"(r) : "r"(x)); return r;
}
__device__ __forceinline__ uint32_t swz(uint32_t base, int row, int chunk) {
    return base + (uint32_t)row * 128u + ((uint32_t)((chunk ^ (row & 7))) << 4);
}
__device__ __forceinline__ void ldsm_x4(uint32_t addr, uint32_t* r) {
    asm volatile("ldmatrix.sync.aligned.m8n8.x4.shared.b16 {%0,%1,%2,%3}, [%4];"
                 : "=r"(r[0]), "=r"(r[1]), "=r"(r[2]), "=r"(r[3]) : "r"(addr));
}
__device__ __forceinline__ void ldsm_x4_t(uint32_t addr, uint32_t* r) {
    asm volatile("ldmatrix.sync.aligned.m8n8.x4.trans.shared.b16 {%0,%1,%2,%3}, [%4];"
                 : "=r"(r[0]), "=r"(r[1]), "=r"(r[2]), "=r"(r[3]) : "r"(addr));
}
__device__ __forceinline__ void mma16816(float* c, const uint32_t* a, uint32_t b0, uint32_t b1) {
    asm volatile("mma.sync.aligned.m16n8k16.row.col.f32.f16.f16.f32 "
                 "{%0,%1,%2,%3}, {%4,%5,%6,%7}, {%8,%9}, {%0,%1,%2,%3};"
                 : "+f"(c[0]), "+f"(c[1]), "+f"(c[2]), "+f"(c[3])
                 : "r"(a[0]), "r"(a[1]), "r"(a[2]), "r"(a[3]), "r"(b0), "r"(b1));
}
__device__ __forceinline__ void cp16(uint32_t dst, const void* src) {
    asm volatile("cp.async.cg.shared.global [%0], [%1], 16;" :: "r"(dst), "l"(src));
}
#define CP_COMMIT() asm volatile("cp.async.commit_group;" ::: "memory")
#define CP_WAIT1()  asm volatile("cp.async.wait_group 1;" ::: "memory")
#define CP_WAIT0()  asm volatile("cp.async.wait_group 0;" ::: "memory")

// tile visit order: diagonal pair first (2qt, 2qt+1), then 2qt-1 .. 0
__device__ __forceinline__ int tile_of(int i, int qt2) {
    return (i == 0) ? qt2 : (i == 1) ? (qt2 + 1) : (qt2 + 1 - i);
}

// ======================= preconvert K,V -> fp16 =======================
__global__ __launch_bounds__(256)
void preconvert_kernel(const float* __restrict__ K, const float* __restrict__ V)
{
    size_t i = (size_t)blockIdx.x * blockDim.x + threadIdx.x;
    if (i >= KV_ELEMS / 4) return;
    {
        float4 x = ((const float4*)K)[i];
        ((uint2*)g_KH)[i] = make_uint2(pack_f16x2(x.x, x.y), pack_f16x2(x.z, x.w));
    }
    {
        float4 x = ((const float4*)V)[i];
        ((uint2*)g_VH)[i] = make_uint2(pack_f16x2(x.x, x.y), pack_f16x2(x.z, x.w));
    }
}

// ============================ flash kernel ============================

__global__ __launch_bounds__(THREADS, 2)
void flash_wmma_kernel(const float* __restrict__ Q, const int* __restrict__ MASK,
                       float* __restrict__ O)
{
    extern __shared__ char smem[];
    const uint32_t sb = smem_u32(smem);
    const int tid = threadIdx.x;
    const int w   = tid >> 5;
    const int ln  = tid & 31;
    const int g   = ln >> 2;
    const int tig = ln & 3;

    // GLOBAL heavy-first: x = bh (fastest), y = qt rank (heavy first)
    const int bh = blockIdx.x;
    const int b  = bh / HEADS;
    const int qt = NQT - 1 - (int)blockIdx.y;
    const int qt2 = 2 * qt;
    const float SC = 0.125f * 1.4426950408889634f;

    const float* Qg = Q + (size_t)bh * S_LEN * D;
    const size_t kvbase = (size_t)bh * S_LEN * D;
    const int*   Mg = MASK + (size_t)b * S_LEN;

    // ---- prologue: stage Q (scaled, fp16, 128x64 = 16KB) into buf0 ----
    {
        const float4* src = (const float4*)(Qg + (size_t)qt * BM * D);
#pragma unroll
        for (int i = 0; i < 16; i++) {
            int f = tid + i * THREADS;
            float4 x = src[f];
            int row = f >> 4, col4 = (f & 15) * 4;
            uint32_t off = (uint32_t)row * 128u
                         + ((uint32_t)(((col4 >> 3) ^ (row & 7))) << 4)
                         + (uint32_t)((col4 & 4) << 1);
            *(uint2*)(smem + off) = make_uint2(pack_f16x2(x.x * SC, x.y * SC),
                                               pack_f16x2(x.z * SC, x.w * SC));
        }
    }
    __syncthreads();

    uint32_t qh[2][4][4];
#pragma unroll
    for (int mt = 0; mt < 2; mt++)
#pragma unroll
        for (int kk = 0; kk < 4; kk++) {
            int row = w * 32 + mt * 16 + (ln & 15);
            int ch  = kk * 2 + (ln >> 4);
            ldsm_x4(swz(sb + SMB(0), row, ch), qh[mt][kk]);
        }
    __syncthreads();

    const int nt_iters = qt2 + 2;

    // ---- prefetch first two tiles in visit order (the diagonal pair) ----
#pragma unroll
    for (int pre = 0; pre < 2; pre++) {
        const int t = tile_of(pre, qt2);
        const size_t tb = kvbase + (size_t)(t * BN) * D;
        const char* pKH = (const char*)(g_KH + tb);
        const char* pVH = (const char*)(g_VH + tb);
        const uint32_t bb = sb + SMB(pre);
#pragma unroll
        for (int i = 0; i < 4; i++) {
            int f = tid + i * THREADS;
            int row = f >> 3, ch = f & 7;
            cp16(swz(bb + OFF_KH, row, ch), pKH + f * 16);
            cp16(swz(bb + OFF_VH, row, ch), pVH + f * 16);
        }
        if (tid < 16) cp16(sb + SM_MASK + pre * 256 + tid * 16, Mg + t * BN + tid * 4);
        CP_COMMIT();
    }

    float o[2][8][4];
#pragma unroll
    for (int mt = 0; mt < 2; mt++)
#pragma unroll
        for (int i = 0; i < 8; i++)
#pragma unroll
            for (int j = 0; j < 4; j++) o[mt][i][j] = 0.0f;
    float ol[2][4] = {{0,0,0,0},{0,0,0,0}};
    float rm[2][2] = {{-1e30f,-1e30f},{-1e30f,-1e30f}};   // frozen after i=1

    const uint32_t ONE2 = 0x3C003C00u;

    for (int i = 0; i < nt_iters; i++) {
        const int t   = tile_of(i, qt2);
        const int buf = i & 1;
        const uint32_t bb = sb + SMB(buf);
        const int* mskp = (const int*)(smem + SM_MASK + buf * 256);

        if (i + 1 < nt_iters) CP_WAIT1(); else CP_WAIT0();
        __syncthreads();

        // ---- S accumulator init: 0 during online phase, -m (frozen bias) after ----
        float s[2][8][4];
        float i00, i01, i10, i11;
        if (i < 2) { i00 = i01 = i10 = i11 = 0.0f; }
        else { i00 = -rm[0][0]; i01 = -rm[0][1]; i10 = -rm[1][0]; i11 = -rm[1][1]; }
#pragma unroll
        for (int nt = 0; nt < 8; nt++) {
            s[0][nt][0] = i00; s[0][nt][1] = i00; s[0][nt][2] = i01; s[0][nt][3] = i01;
            s[1][nt][0] = i10; s[1][nt][1] = i10; s[1][nt][2] = i11; s[1][nt][3] = i11;
#pragma unroll
            for (int h = 0; h < 2; h++) {
                int row = nt * 8 + (ln & 7);
                int ch  = 4 * h + (ln >> 3);
                uint32_t bhf[4];
                ldsm_x4(swz(bb + OFF_KH, row, ch), bhf);
#pragma unroll
                for (int mt = 0; mt < 2; mt++) {
                    mma16816(s[mt][nt], qh[mt][2 * h],     bhf[0], bhf[1]);
                    mma16816(s[mt][nt], qh[mt][2 * h + 1], bhf[2], bhf[3]);
                }
            }
        }

        const bool allv = __all_sync(0xFFFFFFFFu,
                                     (mskp[ln] != 0) && (mskp[ln + 32] != 0));

        if (i < 2) {
            // ======== online phase (diagonal pair): monolithic R13 path ========
            const int coff = (t - qt2) * BN;
            {
#pragma unroll
                for (int mt = 0; mt < 2; mt++) {
                    const int r0 = w * 32 + mt * 16 + g;
                    const int r1 = r0 + 8;
#pragma unroll
                    for (int nt = 0; nt < 8; nt++) {
                        int c0 = nt * 8 + tig * 2 + coff;
                        int mv0 = allv ? 1 : mskp[nt * 8 + tig * 2];
                        int mv1 = allv ? 1 : mskp[nt * 8 + tig * 2 + 1];
                        if (mv0 == 0 || (c0     > r0)) s[mt][nt][0] = -1e30f;
                        if (mv1 == 0 || (c0 + 1 > r0)) s[mt][nt][1] = -1e30f;
                        if (mv0 == 0 || (c0     > r1)) s[mt][nt][2] = -1e30f;
                        if (mv1 == 0 || (c0 + 1 > r1)) s[mt][nt][3] = -1e30f;
                    }
                }
            }
            uint32_t ph[2][4][4];
#pragma unroll
            for (int mt = 0; mt < 2; mt++) {
                float mt0 = rm[mt][0], mt1 = rm[mt][1];
#pragma unroll
                for (int nt = 0; nt < 8; nt++) {
                    mt0 = fmaxf(mt0, fmaxf(s[mt][nt][0], s[mt][nt][1]));
                    mt1 = fmaxf(mt1, fmaxf(s[mt][nt][2], s[mt][nt][3]));
                }
                mt0 = fmaxf(mt0, __shfl_xor_sync(0xFFFFFFFF, mt0, 1));
                mt0 = fmaxf(mt0, __shfl_xor_sync(0xFFFFFFFF, mt0, 2));
                mt1 = fmaxf(mt1, __shfl_xor_sync(0xFFFFFFFF, mt1, 1));
                mt1 = fmaxf(mt1, __shfl_xor_sync(0xFFFFFFFF, mt1, 2));

                const float a0 = ex2f(rm[mt][0] - mt0);
                const float a1 = ex2f(rm[mt][1] - mt1);
                rm[mt][0] = mt0; rm[mt][1] = mt1;

#pragma unroll
                for (int kk = 0; kk < 4; kk++) {
                    ph[mt][kk][0] = ex2_f16x2(pack_f16x2(s[mt][2 * kk][0] - mt0,     s[mt][2 * kk][1] - mt0));
                    ph[mt][kk][1] = ex2_f16x2(pack_f16x2(s[mt][2 * kk][2] - mt1,     s[mt][2 * kk][3] - mt1));
                    ph[mt][kk][2] = ex2_f16x2(pack_f16x2(s[mt][2 * kk + 1][0] - mt0, s[mt][2 * kk + 1][1] - mt0));
                    ph[mt][kk][3] = ex2_f16x2(pack_f16x2(s[mt][2 * kk + 1][2] - mt1, s[mt][2 * kk + 1][3] - mt1));
                }
#pragma unroll
                for (int dt = 0; dt < 8; dt++) {
                    o[mt][dt][0] *= a0; o[mt][dt][1] *= a0;
                    o[mt][dt][2] *= a1; o[mt][dt][3] *= a1;
                }
                ol[mt][0] *= a0; ol[mt][1] *= a0; ol[mt][2] *= a1; ol[mt][3] *= a1;
            }
#pragma unroll
            for (int dt = 0; dt < 8; dt++) {
#pragma unroll
                for (int h = 0; h < 2; h++) {
                    uint32_t vh[4];
                    int row = h * 32 + ln;
                    ldsm_x4_t(swz(bb + OFF_VH, row, dt), vh);
#pragma unroll
                    for (int mt = 0; mt < 2; mt++) {
                        mma16816(o[mt][dt], ph[mt][2 * h],     vh[0], vh[1]);
                        mma16816(o[mt][dt], ph[mt][2 * h + 1], vh[2], vh[3]);
                    }
                }
            }
#pragma unroll
            for (int mt = 0; mt < 2; mt++) {
                mma16816(ol[mt], ph[mt][0], ONE2, ONE2);
                mma16816(ol[mt], ph[mt][1], ONE2, ONE2);
                mma16816(ol[mt], ph[mt][2], ONE2, ONE2);
                mma16816(ol[mt], ph[mt][3], ONE2, ONE2);
            }
        } else {
            // ======== frozen phase: split-softmax pipelined ========
            if (!allv) {
#pragma unroll
                for (int mt = 0; mt < 2; mt++)
#pragma unroll
                    for (int nt = 0; nt < 8; nt++) {
                        int mv0 = mskp[nt * 8 + tig * 2];
                        int mv1 = mskp[nt * 8 + tig * 2 + 1];
                        if (mv0 == 0) { s[mt][nt][0] = -1e30f; s[mt][nt][2] = -1e30f; }
                        if (mv1 == 0) { s[mt][nt][1] = -1e30f; s[mt][nt][3] = -1e30f; }
                    }
            }

            uint32_t ph[2][4][4];
            // -- half 0: exp for cols 0..31 (kk 0,1) --
#pragma unroll
            for (int mt = 0; mt < 2; mt++)
#pragma unroll
                for (int kk = 0; kk < 2; kk++) {
                    ph[mt][kk][0] = ex2_f16x2(pack_f16x2(s[mt][2 * kk][0],     s[mt][2 * kk][1]));
                    ph[mt][kk][1] = ex2_f16x2(pack_f16x2(s[mt][2 * kk][2],     s[mt][2 * kk][3]));
                    ph[mt][kk][2] = ex2_f16x2(pack_f16x2(s[mt][2 * kk + 1][0], s[mt][2 * kk + 1][1]));
                    ph[mt][kk][3] = ex2_f16x2(pack_f16x2(s[mt][2 * kk + 1][2], s[mt][2 * kk + 1][3]));
                }
            // -- PV h=0 issued; drains while half-1 exp executes --
#pragma unroll
            for (int dt = 0; dt < 8; dt++) {
                uint32_t vh[4];
                ldsm_x4_t(swz(bb + OFF_VH, ln, dt), vh);
#pragma unroll
                for (int mt = 0; mt < 2; mt++) {
                    mma16816(o[mt][dt], ph[mt][0], vh[0], vh[1]);
                    mma16816(o[mt][dt], ph[mt][1], vh[2], vh[3]);
                }
            }
#pragma unroll
            for (int mt = 0; mt < 2; mt++) {
                mma16816(ol[mt], ph[mt][0], ONE2, ONE2);
                mma16816(ol[mt], ph[mt][1], ONE2, ONE2);
            }
            // -- half 1: exp for cols 32..63 (kk 2,3), overlaps PV h=0 drain --
#pragma unroll
            for (int mt = 0; mt < 2; mt++)
#pragma unroll
                for (int kk = 2; kk < 4; kk++) {
                    ph[mt][kk][0] = ex2_f16x2(pack_f16x2(s[mt][2 * kk][0],     s[mt][2 * kk][1]));
                    ph[mt][kk][1] = ex2_f16x2(pack_f16x2(s[mt][2 * kk][2],     s[mt][2 * kk][3]));
                    ph[mt][kk][2] = ex2_f16x2(pack_f16x2(s[mt][2 * kk + 1][0], s[mt][2 * kk + 1][1]));
                    ph[mt][kk][3] = ex2_f16x2(pack_f16x2(s[mt][2 * kk + 1][2], s[mt][2 * kk + 1][3]));
                }
            // -- PV h=1 --
#pragma unroll
            for (int dt = 0; dt < 8; dt++) {
                uint32_t vh[4];
                ldsm_x4_t(swz(bb + OFF_VH, 32 + ln, dt), vh);
#pragma unroll
                for (int mt = 0; mt < 2; mt++) {
                    mma16816(o[mt][dt], ph[mt][2], vh[0], vh[1]);
                    mma16816(o[mt][dt], ph[mt][3], vh[2], vh[3]);
                }
            }
#pragma unroll
            for (int mt = 0; mt < 2; mt++) {
                mma16816(ol[mt], ph[mt][2], ONE2, ONE2);
                mma16816(ol[mt], ph[mt][3], ONE2, ONE2);
            }
        }

        __syncthreads();

        // ---- prefetch tile for visit index i+2 ----
        if (i + 2 < nt_iters) {
            const int tn = tile_of(i + 2, qt2);
            const size_t tb = kvbase + (size_t)(tn * BN) * D;
            const char* pKH = (const char*)(g_KH + tb);
            const char* pVH = (const char*)(g_VH + tb);
#pragma unroll
            for (int ii = 0; ii < 4; ii++) {
                int f = tid + ii * THREADS;
                int row = f >> 3, ch = f & 7;
                cp16(swz(bb + OFF_KH, row, ch), pKH + f * 16);
                cp16(swz(bb + OFF_VH, row, ch), pVH + f * 16);
            }
            if (tid < 16) cp16(sb + SM_MASK + buf * 256 + tid * 16, Mg + tn * BN + tid * 4);
            CP_COMMIT();
        }
    }

    // ---- epilogue ----
#pragma unroll
    for (int mt = 0; mt < 2; mt++) {
        const float inv0 = 1.0f / ol[mt][0];
        const float inv1 = 1.0f / ol[mt][2];
        const int row0 = qt * BM + w * 32 + mt * 16 + g;
        const int row1 = row0 + 8;
        float* O0 = O + ((size_t)bh * S_LEN + row0) * D;
        float* O1 = O + ((size_t)bh * S_LEN + row1) * D;
#pragma unroll
        for (int dt = 0; dt < 8; dt++) {
            int c = dt * 8 + tig * 2;
            *(float2*)(O0 + c) = make_float2(o[mt][dt][0] * inv0, o[mt][dt][1] * inv0);
            *(float2*)(O1 + c) = make_float2(o[mt][dt][2] * inv1, o[mt][dt][3] * inv1);
        }
    }
}

extern "C" void kernel_launch(void* const* d_in, const int* in_sizes, int n_in,
                              void* d_out, int out_size)
{
    const float* q = (const float*)d_in[0];
    const float* k = (const float*)d_in[1];
    const float* v = (const float*)d_in[2];
    const int*   msk = (const int*)d_in[3];
    float*       o = (float*)d_out;

    preconvert_kernel<<<(KV_ELEMS / 4 + 255) / 256, 256>>>(k, v);

    cudaFuncSetAttribute(flash_wmma_kernel, cudaFuncAttributeMaxDynamicSharedMemorySize, SM_TOTAL);
    dim3 grid(BHT, NQT);   // x = bh, y = qt rank -> global heavy-first (LPT)
    flash_wmma_kernel<<<grid, THREADS, SM_TOTAL>>>(q, msk, o);
}

// round 15
// speedup vs baseline: 1.0161x; 1.0161x over previous
#include <cuda_runtime.h>
#include <cuda_fp16.h>
#include <cstdint>

// ============================================================================
// Causal attention B=4 H=16 S=2048 D=64 fp32.
// Round 15: R13 compute (LPT launch, frozen-max softmax, fp16 MMAs, ones-col
// row-sum) + 4-deep smem ring: ONE __syncthreads per iteration and prefetch
// issued at loop top (full-iteration cp.async latency cover).
// ============================================================================

#define S_LEN   2048
#define HEADS   16
#define BHT     64
#define D       64
#define BM      128
#define BN      64
#define NQT     (S_LEN / BM)    // 16
#define THREADS 128

#define KV_ELEMS (BHT * S_LEN * D)    // 8,388,608

__device__ __half g_KH[KV_ELEMS];
__device__ __half g_VH[KV_ELEMS];

#define SMB(b)     ((b) * 16384)
#define OFF_KH     0
#define OFF_VH     8192
#define SM_MASK    65536            // 4 x 256B int masks
#define SM_TOTAL   66560

__device__ __forceinline__ uint32_t smem_u32(const void* p) {
    uint32_t a;
    asm("{ .reg .u64 t; cvta.to.shared.u64 t, %1; cvt.u32.u64 %0, t; }" : "=r"(a) : "l"(p));
    return a;
}
__device__ __forceinline__ float ex2f(float x) {
    float y; asm("ex2.approx.f32 %0, %1;" : "=f"(y) : "f"(x)); return y;
}
__device__ __forceinline__ uint32_t pack_f16x2(float e0, float e1) {
    uint32_t r; asm("cvt.rn.f16x2.f32 %0, %1, %2;" : "=r"(r) : "f"(e1), "f"(e0)); return r;
}
__device__ __forceinline__ uint32_t ex2_f16x2(uint32_t x) {
    uint32_t r; asm("ex2.approx.f16x2 %0, %1;" : "=r"(r) : "r"(x)); return r;
}
__device__ __forceinline__ uint32_t swz(uint32_t base, int row, int chunk) {
    return base + (uint32_t)row * 128u + ((uint32_t)((chunk ^ (row & 7))) << 4);
}
__device__ __forceinline__ void ldsm_x4(uint32_t addr, uint32_t* r) {
    asm volatile("ldmatrix.sync.aligned.m8n8.x4.shared.b16 {%0,%1,%2,%3}, [%4];"
                 : "=r"(r[0]), "=r"(r[1]), "=r"(r[2]), "=r"(r[3]) : "r"(addr));
}
__device__ __forceinline__ void ldsm_x4_t(uint32_t addr, uint32_t* r) {
    asm volatile("ldmatrix.sync.aligned.m8n8.x4.trans.shared.b16 {%0,%1,%2,%3}, [%4];"
                 : "=r"(r[0]), "=r"(r[1]), "=r"(r[2]), "=r"(r[3]) : "r"(addr));
}
__device__ __forceinline__ void mma16816(float* c, const uint32_t* a, uint32_t b0, uint32_t b1) {
    asm volatile("mma.sync.aligned.m16n8k16.row.col.f32.f16.f16.f32 "
                 "{%0,%1,%2,%3}, {%4,%5,%6,%7}, {%8,%9}, {%0,%1,%2,%3};"
                 : "+f"(c[0]), "+f"(c[1]), "+f"(c[2]), "+f"(c[3])
                 : "r"(a[0]), "r"(a[1]), "r"(a[2]), "r"(a[3]), "r"(b0), "r"(b1));
}
__device__ __forceinline__ void cp16(uint32_t dst, const void* src) {
    asm volatile("cp.async.cg.shared.global [%0], [%1], 16;" :: "r"(dst), "l"(src));
}
#define CP_COMMIT() asm volatile("cp.async.commit_group;" ::: "memory")
#define CP_WAIT1()  asm volatile("cp.async.wait_group 1;" ::: "memory")
#define CP_WAIT0()  asm volatile("cp.async.wait_group 0;" ::: "memory")

// tile visit order: diagonal pair first (2qt, 2qt+1), then 2qt-1 .. 0
__device__ __forceinline__ int tile_of(int i, int qt2) {
    return (i == 0) ? qt2 : (i == 1) ? (qt2 + 1) : (qt2 + 1 - i);
}

// ======================= preconvert K,V -> fp16 =======================
__global__ __launch_bounds__(256)
void preconvert_kernel(const float* __restrict__ K, const float* __restrict__ V)
{
    size_t i = (size_t)blockIdx.x * blockDim.x + threadIdx.x;
    if (i >= KV_ELEMS / 4) return;
    {
        float4 x = ((const float4*)K)[i];
        ((uint2*)g_KH)[i] = make_uint2(pack_f16x2(x.x, x.y), pack_f16x2(x.z, x.w));
    }
    {
        float4 x = ((const float4*)V)[i];
        ((uint2*)g_VH)[i] = make_uint2(pack_f16x2(x.x, x.y), pack_f16x2(x.z, x.w));
    }
}

// ============================ flash kernel ============================

__global__ __launch_bounds__(THREADS, 2)
void flash_wmma_kernel(const float* __restrict__ Q, const int* __restrict__ MASK,
                       float* __restrict__ O)
{
    extern __shared__ char smem[];
    const uint32_t sb = smem_u32(smem);
    const int tid = threadIdx.x;
    const int w   = tid >> 5;
    const int ln  = tid & 31;
    const int g   = ln >> 2;
    const int tig = ln & 3;

    // GLOBAL heavy-first: x = bh (fastest), y = qt rank (heavy first)
    const int bh = blockIdx.x;
    const int b  = bh / HEADS;
    const int qt = NQT - 1 - (int)blockIdx.y;
    const int qt2 = 2 * qt;
    const float SC = 0.125f * 1.4426950408889634f;

    const float* Qg = Q + (size_t)bh * S_LEN * D;
    const size_t kvbase = (size_t)bh * S_LEN * D;
    const int*   Mg = MASK + (size_t)b * S_LEN;

    // ---- prologue: stage Q (scaled, fp16, 128x64 = 16KB) into b0 ----
    {
        const float4* src = (const float4*)(Qg + (size_t)qt * BM * D);
#pragma unroll
        for (int i = 0; i < 16; i++) {
            int f = tid + i * THREADS;
            float4 x = src[f];
            int row = f >> 4, col4 = (f & 15) * 4;
            uint32_t off = (uint32_t)row * 128u
                         + ((uint32_t)(((col4 >> 3) ^ (row & 7))) << 4)
                         + (uint32_t)((col4 & 4) << 1);
            *(uint2*)(smem + off) = make_uint2(pack_f16x2(x.x * SC, x.y * SC),
                                               pack_f16x2(x.z * SC, x.w * SC));
        }
    }
    __syncthreads();

    uint32_t qh[2][4][4];
#pragma unroll
    for (int mt = 0; mt < 2; mt++)
#pragma unroll
        for (int kk = 0; kk < 4; kk++) {
            int row = w * 32 + mt * 16 + (ln & 15);
            int ch  = kk * 2 + (ln >> 4);
            ldsm_x4(swz(sb + SMB(0), row, ch), qh[mt][kk]);
        }
    __syncthreads();   // Q fragment reads done before cp.async overwrites b0

    const int nt_iters = qt2 + 2;

    // ---- prefetch T(0)->b0, T(1)->b1 ----
#pragma unroll
    for (int pre = 0; pre < 2; pre++) {
        const int t = tile_of(pre, qt2);
        const size_t tb = kvbase + (size_t)(t * BN) * D;
        const char* pKH = (const char*)(g_KH + tb);
        const char* pVH = (const char*)(g_VH + tb);
        const uint32_t bb = sb + SMB(pre);
#pragma unroll
        for (int i = 0; i < 4; i++) {
            int f = tid + i * THREADS;
            int row = f >> 3, ch = f & 7;
            cp16(swz(bb + OFF_KH, row, ch), pKH + f * 16);
            cp16(swz(bb + OFF_VH, row, ch), pVH + f * 16);
        }
        if (tid < 16) cp16(sb + SM_MASK + pre * 256 + tid * 16, Mg + t * BN + tid * 4);
        CP_COMMIT();
    }

    float o[2][8][4];
#pragma unroll
    for (int mt = 0; mt < 2; mt++)
#pragma unroll
        for (int i = 0; i < 8; i++)
#pragma unroll
            for (int j = 0; j < 4; j++) o[mt][i][j] = 0.0f;
    float ol[2][4] = {{0,0,0,0},{0,0,0,0}};
    float rm[2][2] = {{-1e30f,-1e30f},{-1e30f,-1e30f}};   // frozen after i=1

    const uint32_t ONE2 = 0x3C003C00u;

    for (int i = 0; i < nt_iters; i++) {
        const int t  = tile_of(i, qt2);
        const uint32_t bb = sb + SMB(i & 3);
        const int* mskp = (const int*)(smem + SM_MASK + (i & 3) * 256);

        // T(i) resident after this wait (only T(i+1) may remain outstanding)
        if (i + 1 < nt_iters) CP_WAIT1(); else CP_WAIT0();
        __syncthreads();   // copies visible; buf (i+2)&3 last read at iter i-2 — free

        // ---- EARLY prefetch T(i+2) into b((i+2)&3): full iteration of cover ----
        if (i + 2 < nt_iters) {
            const int tn = tile_of(i + 2, qt2);
            const size_t tb = kvbase + (size_t)(tn * BN) * D;
            const char* pKH = (const char*)(g_KH + tb);
            const char* pVH = (const char*)(g_VH + tb);
            const uint32_t bn = sb + SMB((i + 2) & 3);
#pragma unroll
            for (int ii = 0; ii < 4; ii++) {
                int f = tid + ii * THREADS;
                int row = f >> 3, ch = f & 7;
                cp16(swz(bn + OFF_KH, row, ch), pKH + f * 16);
                cp16(swz(bn + OFF_VH, row, ch), pVH + f * 16);
            }
            if (tid < 16)
                cp16(sb + SM_MASK + ((i + 2) & 3) * 256 + tid * 16, Mg + tn * BN + tid * 4);
            CP_COMMIT();
        }

        // ---- S accumulator init: 0 during online phase, -m (frozen bias) after ----
        float s[2][8][4];
        float i00, i01, i10, i11;
        if (i < 2) { i00 = i01 = i10 = i11 = 0.0f; }
        else { i00 = -rm[0][0]; i01 = -rm[0][1]; i10 = -rm[1][0]; i11 = -rm[1][1]; }
#pragma unroll
        for (int nt = 0; nt < 8; nt++) {
            s[0][nt][0] = i00; s[0][nt][1] = i00; s[0][nt][2] = i01; s[0][nt][3] = i01;
            s[1][nt][0] = i10; s[1][nt][1] = i10; s[1][nt][2] = i11; s[1][nt][3] = i11;
#pragma unroll
            for (int h = 0; h < 2; h++) {
                int row = nt * 8 + (ln & 7);
                int ch  = 4 * h + (ln >> 3);
                uint32_t bhf[4];
                ldsm_x4(swz(bb + OFF_KH, row, ch), bhf);
#pragma unroll
                for (int mt = 0; mt < 2; mt++) {
                    mma16816(s[mt][nt], qh[mt][2 * h],     bhf[0], bhf[1]);
                    mma16816(s[mt][nt], qh[mt][2 * h + 1], bhf[2], bhf[3]);
                }
            }
        }

        // ---- mask + causal (causal iff diagonal pair, i < 2) ----
        const bool causal = (i < 2);
        const int  coff   = (t - qt2) * BN;
        const bool allv = __all_sync(0xFFFFFFFFu,
                                     (mskp[ln] != 0) && (mskp[ln + 32] != 0));
        if (causal || !allv) {
#pragma unroll
            for (int mt = 0; mt < 2; mt++) {
                const int r0 = w * 32 + mt * 16 + g;
                const int r1 = r0 + 8;
#pragma unroll
                for (int nt = 0; nt < 8; nt++) {
                    int c0 = nt * 8 + tig * 2 + coff;
                    int mv0 = allv ? 1 : mskp[nt * 8 + tig * 2];
                    int mv1 = allv ? 1 : mskp[nt * 8 + tig * 2 + 1];
                    if (mv0 == 0 || (causal && c0     > r0)) s[mt][nt][0] = -1e30f;
                    if (mv1 == 0 || (causal && c0 + 1 > r0)) s[mt][nt][1] = -1e30f;
                    if (mv0 == 0 || (causal && c0     > r1)) s[mt][nt][2] = -1e30f;
                    if (mv1 == 0 || (causal && c0 + 1 > r1)) s[mt][nt][3] = -1e30f;
                }
            }
        }

        // ---- softmax ----
        uint32_t ph[2][4][4];
        if (i < 2) {
#pragma unroll
            for (int mt = 0; mt < 2; mt++) {
                float mt0 = rm[mt][0], mt1 = rm[mt][1];
#pragma unroll
                for (int nt = 0; nt < 8; nt++) {
                    mt0 = fmaxf(mt0, fmaxf(s[mt][nt][0], s[mt][nt][1]));
                    mt1 = fmaxf(mt1, fmaxf(s[mt][nt][2], s[mt][nt][3]));
                }
                mt0 = fmaxf(mt0, __shfl_xor_sync(0xFFFFFFFF, mt0, 1));
                mt0 = fmaxf(mt0, __shfl_xor_sync(0xFFFFFFFF, mt0, 2));
                mt1 = fmaxf(mt1, __shfl_xor_sync(0xFFFFFFFF, mt1, 1));
                mt1 = fmaxf(mt1, __shfl_xor_sync(0xFFFFFFFF, mt1, 2));

                const float a0 = ex2f(rm[mt][0] - mt0);
                const float a1 = ex2f(rm[mt][1] - mt1);
                rm[mt][0] = mt0; rm[mt][1] = mt1;

#pragma unroll
                for (int kk = 0; kk < 4; kk++) {
                    ph[mt][kk][0] = ex2_f16x2(pack_f16x2(s[mt][2 * kk][0] - mt0,     s[mt][2 * kk][1] - mt0));
                    ph[mt][kk][1] = ex2_f16x2(pack_f16x2(s[mt][2 * kk][2] - mt1,     s[mt][2 * kk][3] - mt1));
                    ph[mt][kk][2] = ex2_f16x2(pack_f16x2(s[mt][2 * kk + 1][0] - mt0, s[mt][2 * kk + 1][1] - mt0));
                    ph[mt][kk][3] = ex2_f16x2(pack_f16x2(s[mt][2 * kk + 1][2] - mt1, s[mt][2 * kk + 1][3] - mt1));
                }
#pragma unroll
                for (int dt = 0; dt < 8; dt++) {
                    o[mt][dt][0] *= a0; o[mt][dt][1] *= a0;
                    o[mt][dt][2] *= a1; o[mt][dt][3] *= a1;
                }
                ol[mt][0] *= a0; ol[mt][1] *= a0; ol[mt][2] *= a1; ol[mt][3] *= a1;
            }
        } else {
#pragma unroll
            for (int mt = 0; mt < 2; mt++)
#pragma unroll
                for (int kk = 0; kk < 4; kk++) {
                    ph[mt][kk][0] = ex2_f16x2(pack_f16x2(s[mt][2 * kk][0],     s[mt][2 * kk][1]));
                    ph[mt][kk][1] = ex2_f16x2(pack_f16x2(s[mt][2 * kk][2],     s[mt][2 * kk][3]));
                    ph[mt][kk][2] = ex2_f16x2(pack_f16x2(s[mt][2 * kk + 1][0], s[mt][2 * kk + 1][1]));
                    ph[mt][kk][3] = ex2_f16x2(pack_f16x2(s[mt][2 * kk + 1][2], s[mt][2 * kk + 1][3]));
                }
        }

        // ---- O += Ph Vh; l += Ph * ones ----
#pragma unroll
        for (int dt = 0; dt < 8; dt++) {
#pragma unroll
            for (int h = 0; h < 2; h++) {
                uint32_t vh[4];
                int row = h * 32 + ln;
                ldsm_x4_t(swz(bb + OFF_VH, row, dt), vh);
#pragma unroll
                for (int mt = 0; mt < 2; mt++) {
                    mma16816(o[mt][dt], ph[mt][2 * h],     vh[0], vh[1]);
                    mma16816(o[mt][dt], ph[mt][2 * h + 1], vh[2], vh[3]);
                }
            }
        }
#pragma unroll
        for (int mt = 0; mt < 2; mt++) {
            mma16816(ol[mt], ph[mt][0], ONE2, ONE2);
            mma16816(ol[mt], ph[mt][1], ONE2, ONE2);
            mma16816(ol[mt], ph[mt][2], ONE2, ONE2);
            mma16816(ol[mt], ph[mt][3], ONE2, ONE2);
        }
    }

    // ---- epilogue ----
#pragma unroll
    for (int mt = 0; mt < 2; mt++) {
        const float inv0 = 1.0f / ol[mt][0];
        const float inv1 = 1.0f / ol[mt][2];
        const int row0 = qt * BM + w * 32 + mt * 16 + g;
        const int row1 = row0 + 8;
        float* O0 = O + ((size_t)bh * S_LEN + row0) * D;
        float* O1 = O + ((size_t)bh * S_LEN + row1) * D;
#pragma unroll
        for (int dt = 0; dt < 8; dt++) {
            int c = dt * 8 + tig * 2;
            *(float2*)(O0 + c) = make_float2(o[mt][dt][0] * inv0, o[mt][dt][1] * inv0);
            *(float2*)(O1 + c) = make_float2(o[mt][dt][2] * inv1, o[mt][dt][3] * inv1);
        }
    }
}

extern "C" void kernel_launch(void* const* d_in, const int* in_sizes, int n_in,
                              void* d_out, int out_size)
{
    const float* q = (const float*)d_in[0];
    const float* k = (const float*)d_in[1];
    const float* v = (const float*)d_in[2];
    const int*   msk = (const int*)d_in[3];
    float*       o = (float*)d_out;

    preconvert_kernel<<<(KV_ELEMS / 4 + 255) / 256, 256>>>(k, v);

    cudaFuncSetAttribute(flash_wmma_kernel, cudaFuncAttributeMaxDynamicSharedMemorySize, SM_TOTAL);
    dim3 grid(BHT, NQT);   // x = bh, y = qt rank -> global heavy-first (LPT)
    flash_wmma_kernel<<<grid, THREADS, SM_TOTAL>>>(q, msk, o);
}

// round 16
// speedup vs baseline: 1.0299x; 1.0135x over previous
#include <cuda_runtime.h>
#include <cuda_fp16.h>
#include <cstdint>

// ============================================================================
// Causal attention B=4 H=16 S=2048 D=64 fp32.
// Round 16: R15 compute + skew-tolerant split barriers (bar.arrive at iter end
// after wait_group; bar.sync on the PREVIOUS iteration's barrier at iter top).
// Warps may de-phase by up to one iteration, overlapping one warp's softmax
// with another's HMMA stream. 4-deep smem ring guarantees no buffer hazard.
// ============================================================================

#define S_LEN   2048
#define HEADS   16
#define BHT     64
#define D       64
#define BM      128
#define BN      64
#define NQT     (S_LEN / BM)    // 16
#define THREADS 128

#define KV_ELEMS (BHT * S_LEN * D)    // 8,388,608

__device__ __half g_KH[KV_ELEMS];
__device__ __half g_VH[KV_ELEMS];

#define SMB(b)     ((b) * 16384)
#define OFF_KH     0
#define OFF_VH     8192
#define SM_MASK    65536            // 4 x 256B int masks
#define SM_TOTAL   66560

__device__ __forceinline__ uint32_t smem_u32(const void* p) {
    uint32_t a;
    asm("{ .reg .u64 t; cvta.to.shared.u64 t, %1; cvt.u32.u64 %0, t; }" : "=r"(a) : "l"(p));
    return a;
}
__device__ __forceinline__ float ex2f(float x) {
    float y; asm("ex2.approx.f32 %0, %1;" : "=f"(y) : "f"(x)); return y;
}
__device__ __forceinline__ uint32_t pack_f16x2(float e0, float e1) {
    uint32_t r; asm("cvt.rn.f16x2.f32 %0, %1, %2;" : "=r"(r) : "f"(e1), "f"(e0)); return r;
}
__device__ __forceinline__ uint32_t ex2_f16x2(uint32_t x) {
    uint32_t r; asm("ex2.approx.f16x2 %0, %1;" : "=r"(r) : "r"(x)); return r;
}
__device__ __forceinline__ uint32_t swz(uint32_t base, int row, int chunk) {
    return base + (uint32_t)row * 128u + ((uint32_t)((chunk ^ (row & 7))) << 4);
}
__device__ __forceinline__ void ldsm_x4(uint32_t addr, uint32_t* r) {
    asm volatile("ldmatrix.sync.aligned.m8n8.x4.shared.b16 {%0,%1,%2,%3}, [%4];"
                 : "=r"(r[0]), "=r"(r[1]), "=r"(r[2]), "=r"(r[3]) : "r"(addr));
}
__device__ __forceinline__ void ldsm_x4_t(uint32_t addr, uint32_t* r) {
    asm volatile("ldmatrix.sync.aligned.m8n8.x4.trans.shared.b16 {%0,%1,%2,%3}, [%4];"
                 : "=r"(r[0]), "=r"(r[1]), "=r"(r[2]), "=r"(r[3]) : "r"(addr));
}
__device__ __forceinline__ void mma16816(float* c, const uint32_t* a, uint32_t b0, uint32_t b1) {
    asm volatile("mma.sync.aligned.m16n8k16.row.col.f32.f16.f16.f32 "
                 "{%0,%1,%2,%3}, {%4,%5,%6,%7}, {%8,%9}, {%0,%1,%2,%3};"
                 : "+f"(c[0]), "+f"(c[1]), "+f"(c[2]), "+f"(c[3])
                 : "r"(a[0]), "r"(a[1]), "r"(a[2]), "r"(a[3]), "r"(b0), "r"(b1));
}
__device__ __forceinline__ void cp16(uint32_t dst, const void* src) {
    asm volatile("cp.async.cg.shared.global [%0], [%1], 16;" :: "r"(dst), "l"(src));
}
#define CP_COMMIT() asm volatile("cp.async.commit_group;" ::: "memory")
#define CP_WAIT1()  asm volatile("cp.async.wait_group 1;" ::: "memory")
#define CP_WAIT0()  asm volatile("cp.async.wait_group 0;" ::: "memory")

// split named barriers: IDs 1,2 (0 is __syncthreads). 256 arrivals:
// each of 128 threads arrives once (bar.arrive) and syncs once (bar.sync).
#define BAR_ARRIVE(id) asm volatile("bar.arrive %0, 256;" :: "r"(id) : "memory")
#define BAR_SYNC(id)   asm volatile("bar.sync %0, 256;"   :: "r"(id) : "memory")

// tile visit order: diagonal pair first (2qt, 2qt+1), then 2qt-1 .. 0
__device__ __forceinline__ int tile_of(int i, int qt2) {
    return (i == 0) ? qt2 : (i == 1) ? (qt2 + 1) : (qt2 + 1 - i);
}

// ======================= preconvert K,V -> fp16 =======================
__global__ __launch_bounds__(256)
void preconvert_kernel(const float* __restrict__ K, const float* __restrict__ V)
{
    size_t i = (size_t)blockIdx.x * blockDim.x + threadIdx.x;
    if (i >= KV_ELEMS / 4) return;
    {
        float4 x = ((const float4*)K)[i];
        ((uint2*)g_KH)[i] = make_uint2(pack_f16x2(x.x, x.y), pack_f16x2(x.z, x.w));
    }
    {
        float4 x = ((const float4*)V)[i];
        ((uint2*)g_VH)[i] = make_uint2(pack_f16x2(x.x, x.y), pack_f16x2(x.z, x.w));
    }
}

// ============================ flash kernel ============================

__global__ __launch_bounds__(THREADS, 2)
void flash_wmma_kernel(const float* __restrict__ Q, const int* __restrict__ MASK,
                       float* __restrict__ O)
{
    extern __shared__ char smem[];
    const uint32_t sb = smem_u32(smem);
    const int tid = threadIdx.x;
    const int w   = tid >> 5;
    const int ln  = tid & 31;
    const int g   = ln >> 2;
    const int tig = ln & 3;

    // GLOBAL heavy-first: x = bh (fastest), y = qt rank (heavy first)
    const int bh = blockIdx.x;
    const int b  = bh / HEADS;
    const int qt = NQT - 1 - (int)blockIdx.y;
    const int qt2 = 2 * qt;
    const float SC = 0.125f * 1.4426950408889634f;

    const float* Qg = Q + (size_t)bh * S_LEN * D;
    const size_t kvbase = (size_t)bh * S_LEN * D;
    const int*   Mg = MASK + (size_t)b * S_LEN;

    // ---- prologue: stage Q (scaled, fp16, 128x64 = 16KB) into b0 ----
    {
        const float4* src = (const float4*)(Qg + (size_t)qt * BM * D);
#pragma unroll
        for (int i = 0; i < 16; i++) {
            int f = tid + i * THREADS;
            float4 x = src[f];
            int row = f >> 4, col4 = (f & 15) * 4;
            uint32_t off = (uint32_t)row * 128u
                         + ((uint32_t)(((col4 >> 3) ^ (row & 7))) << 4)
                         + (uint32_t)((col4 & 4) << 1);
            *(uint2*)(smem + off) = make_uint2(pack_f16x2(x.x * SC, x.y * SC),
                                               pack_f16x2(x.z * SC, x.w * SC));
        }
    }
    __syncthreads();

    uint32_t qh[2][4][4];
#pragma unroll
    for (int mt = 0; mt < 2; mt++)
#pragma unroll
        for (int kk = 0; kk < 4; kk++) {
            int row = w * 32 + mt * 16 + (ln & 15);
            int ch  = kk * 2 + (ln >> 4);
            ldsm_x4(swz(sb + SMB(0), row, ch), qh[mt][kk]);
        }
    __syncthreads();   // Q fragment reads done before cp.async overwrites b0

    const int nt_iters = qt2 + 2;

    // ---- prefetch T(0)->b0, T(1)->b1 ----
#pragma unroll
    for (int pre = 0; pre < 2; pre++) {
        const int t = tile_of(pre, qt2);
        const size_t tb = kvbase + (size_t)(t * BN) * D;
        const char* pKH = (const char*)(g_KH + tb);
        const char* pVH = (const char*)(g_VH + tb);
        const uint32_t bb = sb + SMB(pre);
#pragma unroll
        for (int i = 0; i < 4; i++) {
            int f = tid + i * THREADS;
            int row = f >> 3, ch = f & 7;
            cp16(swz(bb + OFF_KH, row, ch), pKH + f * 16);
            cp16(swz(bb + OFF_VH, row, ch), pVH + f * 16);
        }
        if (tid < 16) cp16(sb + SM_MASK + pre * 256 + tid * 16, Mg + pre * 0 + t * BN + tid * 4);
        CP_COMMIT();
    }
    CP_WAIT1();          // T(0) retired (T(1) may be in flight)
    __syncthreads();     // T(0) visible to all warps

    float o[2][8][4];
#pragma unroll
    for (int mt = 0; mt < 2; mt++)
#pragma unroll
        for (int i = 0; i < 8; i++)
#pragma unroll
            for (int j = 0; j < 4; j++) o[mt][i][j] = 0.0f;
    float ol[2][4] = {{0,0,0,0},{0,0,0,0}};
    float rm[2][2] = {{-1e30f,-1e30f},{-1e30f,-1e30f}};   // frozen after i=1

    const uint32_t ONE2 = 0x3C003C00u;

    for (int i = 0; i < nt_iters; i++) {
        const int t  = tile_of(i, qt2);
        const uint32_t bb = sb + SMB(i & 3);
        const int* mskp = (const int*)(smem + SM_MASK + (i & 3) * 256);

        // skew-tolerant: wait on PREVIOUS iteration's arrivals (tile T(i) made
        // visible by every warp's wait_group+arrive at end of iter i-1)
        if (i > 0) BAR_SYNC(1 + ((i - 1) & 1));

        // ---- S accumulator init: 0 during online phase, -m (frozen bias) after ----
        float s[2][8][4];
        float i00, i01, i10, i11;
        if (i < 2) { i00 = i01 = i10 = i11 = 0.0f; }
        else { i00 = -rm[0][0]; i01 = -rm[0][1]; i10 = -rm[1][0]; i11 = -rm[1][1]; }
#pragma unroll
        for (int nt = 0; nt < 8; nt++) {
            s[0][nt][0] = i00; s[0][nt][1] = i00; s[0][nt][2] = i01; s[0][nt][3] = i01;
            s[1][nt][0] = i10; s[1][nt][1] = i10; s[1][nt][2] = i11; s[1][nt][3] = i11;
#pragma unroll
            for (int h = 0; h < 2; h++) {
                int row = nt * 8 + (ln & 7);
                int ch  = 4 * h + (ln >> 3);
                uint32_t bhf[4];
                ldsm_x4(swz(bb + OFF_KH, row, ch), bhf);
#pragma unroll
                for (int mt = 0; mt < 2; mt++) {
                    mma16816(s[mt][nt], qh[mt][2 * h],     bhf[0], bhf[1]);
                    mma16816(s[mt][nt], qh[mt][2 * h + 1], bhf[2], bhf[3]);
                }
            }
        }

        // ---- mask + causal (causal iff diagonal pair, i < 2) ----
        const bool causal = (i < 2);
        const int  coff   = (t - qt2) * BN;
        const bool allv = __all_sync(0xFFFFFFFFu,
                                     (mskp[ln] != 0) && (mskp[ln + 32] != 0));
        if (causal || !allv) {
#pragma unroll
            for (int mt = 0; mt < 2; mt++) {
                const int r0 = w * 32 + mt * 16 + g;
                const int r1 = r0 + 8;
#pragma unroll
                for (int nt = 0; nt < 8; nt++) {
                    int c0 = nt * 8 + tig * 2 + coff;
                    int mv0 = allv ? 1 : mskp[nt * 8 + tig * 2];
                    int mv1 = allv ? 1 : mskp[nt * 8 + tig * 2 + 1];
                    if (mv0 == 0 || (causal && c0     > r0)) s[mt][nt][0] = -1e30f;
                    if (mv1 == 0 || (causal && c0 + 1 > r0)) s[mt][nt][1] = -1e30f;
                    if (mv0 == 0 || (causal && c0     > r1)) s[mt][nt][2] = -1e30f;
                    if (mv1 == 0 || (causal && c0 + 1 > r1)) s[mt][nt][3] = -1e30f;
                }
            }
        }

        // ---- softmax ----
        uint32_t ph[2][4][4];
        if (i < 2) {
#pragma unroll
            for (int mt = 0; mt < 2; mt++) {
                float mt0 = rm[mt][0], mt1 = rm[mt][1];
#pragma unroll
                for (int nt = 0; nt < 8; nt++) {
                    mt0 = fmaxf(mt0, fmaxf(s[mt][nt][0], s[mt][nt][1]));
                    mt1 = fmaxf(mt1, fmaxf(s[mt][nt][2], s[mt][nt][3]));
                }
                mt0 = fmaxf(mt0, __shfl_xor_sync(0xFFFFFFFF, mt0, 1));
                mt0 = fmaxf(mt0, __shfl_xor_sync(0xFFFFFFFF, mt0, 2));
                mt1 = fmaxf(mt1, __shfl_xor_sync(0xFFFFFFFF, mt1, 1));
                mt1 = fmaxf(mt1, __shfl_xor_sync(0xFFFFFFFF, mt1, 2));

                const float a0 = ex2f(rm[mt][0] - mt0);
                const float a1 = ex2f(rm[mt][1] - mt1);
                rm[mt][0] = mt0; rm[mt][1] = mt1;

#pragma unroll
                for (int kk = 0; kk < 4; kk++) {
                    ph[mt][kk][0] = ex2_f16x2(pack_f16x2(s[mt][2 * kk][0] - mt0,     s[mt][2 * kk][1] - mt0));
                    ph[mt][kk][1] = ex2_f16x2(pack_f16x2(s[mt][2 * kk][2] - mt1,     s[mt][2 * kk][3] - mt1));
                    ph[mt][kk][2] = ex2_f16x2(pack_f16x2(s[mt][2 * kk + 1][0] - mt0, s[mt][2 * kk + 1][1] - mt0));
                    ph[mt][kk][3] = ex2_f16x2(pack_f16x2(s[mt][2 * kk + 1][2] - mt1, s[mt][2 * kk + 1][3] - mt1));
                }
#pragma unroll
                for (int dt = 0; dt < 8; dt++) {
                    o[mt][dt][0] *= a0; o[mt][dt][1] *= a0;
                    o[mt][dt][2] *= a1; o[mt][dt][3] *= a1;
                }
                ol[mt][0] *= a0; ol[mt][1] *= a0; ol[mt][2] *= a1; ol[mt][3] *= a1;
            }
        } else {
#pragma unroll
            for (int mt = 0; mt < 2; mt++)
#pragma unroll
                for (int kk = 0; kk < 4; kk++) {
                    ph[mt][kk][0] = ex2_f16x2(pack_f16x2(s[mt][2 * kk][0],     s[mt][2 * kk][1]));
                    ph[mt][kk][1] = ex2_f16x2(pack_f16x2(s[mt][2 * kk][2],     s[mt][2 * kk][3]));
                    ph[mt][kk][2] = ex2_f16x2(pack_f16x2(s[mt][2 * kk + 1][0], s[mt][2 * kk + 1][1]));
                    ph[mt][kk][3] = ex2_f16x2(pack_f16x2(s[mt][2 * kk + 1][2], s[mt][2 * kk + 1][3]));
                }
        }

        // ---- O += Ph Vh; l += Ph * ones ----
#pragma unroll
        for (int dt = 0; dt < 8; dt++) {
#pragma unroll
            for (int h = 0; h < 2; h++) {
                uint32_t vh[4];
                int row = h * 32 + ln;
                ldsm_x4_t(swz(bb + OFF_VH, row, dt), vh);
#pragma unroll
                for (int mt = 0; mt < 2; mt++) {
                    mma16816(o[mt][dt], ph[mt][2 * h],     vh[0], vh[1]);
                    mma16816(o[mt][dt], ph[mt][2 * h + 1], vh[2], vh[3]);
                }
            }
        }
#pragma unroll
        for (int mt = 0; mt < 2; mt++) {
            mma16816(ol[mt], ph[mt][0], ONE2, ONE2);
            mma16816(ol[mt], ph[mt][1], ONE2, ONE2);
            mma16816(ol[mt], ph[mt][2], ONE2, ONE2);
            mma16816(ol[mt], ph[mt][3], ONE2, ONE2);
        }

        // ---- iter end: prefetch T(i+2), retire T(i+1), arrive ----
        if (i + 1 < nt_iters) {
            if (i + 2 < nt_iters) {
                const int tn = tile_of(i + 2, qt2);
                const size_t tb = kvbase + (size_t)(tn * BN) * D;
                const char* pKH = (const char*)(g_KH + tb);
                const char* pVH = (const char*)(g_VH + tb);
                const uint32_t bn = sb + SMB((i + 2) & 3);
#pragma unroll
                for (int ii = 0; ii < 4; ii++) {
                    int f = tid + ii * THREADS;
                    int row = f >> 3, ch = f & 7;
                    cp16(swz(bn + OFF_KH, row, ch), pKH + f * 16);
                    cp16(swz(bn + OFF_VH, row, ch), pVH + f * 16);
                }
                if (tid < 16)
                    cp16(sb + SM_MASK + ((i + 2) & 3) * 256 + tid * 16, Mg + tn * BN + tid * 4);
                CP_COMMIT();
                CP_WAIT1();    // retire T(i+1); T(i+2) stays in flight
            } else {
                CP_WAIT0();    // retire T(i+1) (last tile)
            }
            BAR_ARRIVE(1 + (i & 1));
        }
    }

    // ---- epilogue ----
#pragma unroll
    for (int mt = 0; mt < 2; mt++) {
        const float inv0 = 1.0f / ol[mt][0];
        const float inv1 = 1.0f / ol[mt][2];
        const int row0 = qt * BM + w * 32 + mt * 16 + g;
        const int row1 = row0 + 8;
        float* O0 = O + ((size_t)bh * S_LEN + row0) * D;
        float* O1 = O + ((size_t)bh * S_LEN + row1) * D;
#pragma unroll
        for (int dt = 0; dt < 8; dt++) {
            int c = dt * 8 + tig * 2;
            *(float2*)(O0 + c) = make_float2(o[mt][dt][0] * inv0, o[mt][dt][1] * inv0);
            *(float2*)(O1 + c) = make_float2(o[mt][dt][2] * inv1, o[mt][dt][3] * inv1);
        }
    }
}

extern "C" void kernel_launch(void* const* d_in, const int* in_sizes, int n_in,
                              void* d_out, int out_size)
{
    const float* q = (const float*)d_in[0];
    const float* k = (const float*)d_in[1];
    const float* v = (const float*)d_in[2];
    const int*   msk = (const int*)d_in[3];
    float*       o = (float*)d_out;

    preconvert_kernel<<<(KV_ELEMS / 4 + 255) / 256, 256>>>(k, v);

    cudaFuncSetAttribute(flash_wmma_kernel, cudaFuncAttributeMaxDynamicSharedMemorySize, SM_TOTAL);
    dim3 grid(BHT, NQT);   // x = bh, y = qt rank -> global heavy-first (LPT)
    flash_wmma_kernel<<<grid, THREADS, SM_TOTAL>>>(q, msk, o);
}